// round 1
// baseline (speedup 1.0000x reference)
#include <cuda_runtime.h>
#include <math.h>

#define N_NODES 100000
#define N_EDGES 640000
#define DIM     128
#define N_GRAPHS 512
#define N_ITEMS (N_EDGES + N_NODES)   // edges + self loops

// ---------------- device scratch (allocation-free) ----------------
__device__ float g_y1[(size_t)N_NODES * DIM];   // Âx, later x3
__device__ float g_y2[(size_t)N_NODES * DIM];   // Â²x
__device__ float g_dinv[N_NODES];
__device__ int   g_deg[N_NODES];
__device__ float g_W12[DIM * DIM];              // W0 @ W1
__device__ float g_z[N_GRAPHS * DIM];           // pooled P·Â·x3

// ---------------- init / degree ----------------
__global__ void k_init() {
    int stride = gridDim.x * blockDim.x;
    for (int idx = blockIdx.x * blockDim.x + threadIdx.x;
         idx < N_NODES * DIM; idx += stride) {
        g_y1[idx] = 0.f;
        g_y2[idx] = 0.f;
        if (idx < N_NODES)       g_deg[idx] = 1;       // self loop
        if (idx < N_GRAPHS * DIM) g_z[idx]  = 0.f;
    }
}

__global__ void k_deg(const int* __restrict__ col) {
    int e = blockIdx.x * blockDim.x + threadIdx.x;
    if (e < N_EDGES) atomicAdd(&g_deg[col[e]], 1);
}

__global__ void k_dinv() {
    int v = blockIdx.x * blockDim.x + threadIdx.x;
    if (v < N_NODES) g_dinv[v] = rsqrtf((float)g_deg[v]);
}

// ---------------- W12 = W0 @ W1 (128x128x128, trivial) ----------------
__global__ void k_w12(const float* __restrict__ W0, const float* __restrict__ W1) {
    int i = blockIdx.x;      // 128 blocks
    int j = threadIdx.x;     // 128 threads
    float acc = 0.f;
    #pragma unroll 8
    for (int k = 0; k < DIM; k++)
        acc += W0[i * DIM + k] * W1[k * DIM + j];
    g_W12[i * DIM + j] = acc;
}

// ---------------- propagation: dst[col] += dinv[row]*dinv[col] * src[row]
// MODE 0: src = x (arg),  dst = g_y1
// MODE 1: src = g_y1,     dst = g_y2
// MODE 2: src = g_y1(x3), dst = g_z pooled via batch[col]
template <int MODE>
__global__ void k_prop(const float* __restrict__ xin,
                       const int* __restrict__ row,
                       const int* __restrict__ col,
                       const int* __restrict__ batch) {
    long long gt = (long long)blockIdx.x * blockDim.x + threadIdx.x;
    int item = (int)(gt >> 5);
    int lane = (int)(gt & 31);
    if (item >= N_ITEMS) return;

    int r, c;
    float norm;
    if (item < N_EDGES) {
        r = row[item];
        c = col[item];
        norm = g_dinv[r] * g_dinv[c];
    } else {                       // self loop
        r = c = item - N_EDGES;
        float dv = g_dinv[r];
        norm = dv * dv;
    }

    const float* src = (MODE == 0) ? xin : g_y1;
    const float4 v = *reinterpret_cast<const float4*>(src + (size_t)r * DIM + lane * 4);
    float4 m = make_float4(v.x * norm, v.y * norm, v.z * norm, v.w * norm);

    float* dst;
    if (MODE == 2) {
        dst = g_z + (size_t)batch[c] * DIM + lane * 4;
    } else {
        float* base = (MODE == 0) ? g_y1 : g_y2;
        dst = base + (size_t)c * DIM + lane * 4;
    }
    asm volatile("red.global.add.v4.f32 [%0], {%1, %2, %3, %4};"
                 :: "l"(dst), "f"(m.x), "f"(m.y), "f"(m.z), "f"(m.w)
                 : "memory");
}

// ---------------- x3 = leaky_relu(g_y2 @ g_W12) -> g_y1 ----------------
// 128x128 C-tile per block, 16x16 threads, 8x8 micro-tile (cols strided by 16
// for conflict-free smem B reads).
__global__ void __launch_bounds__(256) k_gemm_leaky() {
    __shared__ float sA[16][128];   // [k][row]
    __shared__ float sB[16][128];   // [k][col]
    int t  = threadIdx.x;
    int tx = t & 15, ty = t >> 4;
    int i0 = blockIdx.x * 128;

    float acc[8][8];
    #pragma unroll
    for (int m = 0; m < 8; m++)
        #pragma unroll
        for (int n = 0; n < 8; n++) acc[m][n] = 0.f;

    for (int k0 = 0; k0 < DIM; k0 += 16) {
        // A tile: rows i0..i0+127, cols k0..k0+15 (2 float4 per thread)
        #pragma unroll
        for (int l = 0; l < 2; l++) {
            int q    = t + l * 256;       // float4 id 0..511
            int arow = q >> 2;
            int kk4  = (q & 3) * 4;
            float4 v = make_float4(0.f, 0.f, 0.f, 0.f);
            int gr = i0 + arow;
            if (gr < N_NODES)
                v = *reinterpret_cast<const float4*>(
                        &g_y2[(size_t)gr * DIM + k0 + kk4]);
            sA[kk4 + 0][arow] = v.x;
            sA[kk4 + 1][arow] = v.y;
            sA[kk4 + 2][arow] = v.z;
            sA[kk4 + 3][arow] = v.w;
        }
        // B tile: fully coalesced
        #pragma unroll
        for (int l = 0; l < 2; l++) {
            int q  = t + l * 256;
            int kk = q >> 5;
            int j4 = (q & 31) * 4;
            float4 v = *reinterpret_cast<const float4*>(
                           &g_W12[(k0 + kk) * DIM + j4]);
            *reinterpret_cast<float4*>(&sB[kk][j4]) = v;
        }
        __syncthreads();

        #pragma unroll
        for (int k = 0; k < 16; k++) {
            float a[8], b[8];
            float4 a0 = *reinterpret_cast<const float4*>(&sA[k][ty * 8]);
            float4 a1 = *reinterpret_cast<const float4*>(&sA[k][ty * 8 + 4]);
            a[0] = a0.x; a[1] = a0.y; a[2] = a0.z; a[3] = a0.w;
            a[4] = a1.x; a[5] = a1.y; a[6] = a1.z; a[7] = a1.w;
            #pragma unroll
            for (int n = 0; n < 8; n++) b[n] = sB[k][tx + 16 * n];
            #pragma unroll
            for (int m = 0; m < 8; m++)
                #pragma unroll
                for (int n = 0; n < 8; n++)
                    acc[m][n] += a[m] * b[n];
        }
        __syncthreads();
    }

    #pragma unroll
    for (int m = 0; m < 8; m++) {
        int gr = i0 + ty * 8 + m;
        if (gr < N_NODES) {
            #pragma unroll
            for (int n = 0; n < 8; n++) {
                float v = acc[m][n];
                v = (v > 0.f) ? v : 0.01f * v;
                g_y1[(size_t)gr * DIM + tx + 16 * n] = v;
            }
        }
    }
}

// ---------------- out = g_z @ W2  (512x128x128) ----------------
__global__ void k_out(const float* __restrict__ W2, float* __restrict__ out) {
    __shared__ float sz[DIM];
    int g = blockIdx.x;
    int j = threadIdx.x;
    sz[j] = g_z[g * DIM + j];
    __syncthreads();
    float acc = 0.f;
    #pragma unroll 8
    for (int k = 0; k < DIM; k++)
        acc += sz[k] * W2[k * DIM + j];
    out[g * DIM + j] = acc;
}

// ---------------- launch ----------------
extern "C" void kernel_launch(void* const* d_in, const int* in_sizes, int n_in,
                              void* d_out, int out_size) {
    const float* x     = (const float*)d_in[0];
    const int*   ei    = (const int*)d_in[1];
    const int*   batch = (const int*)d_in[2];
    const float* W0    = (const float*)d_in[3];
    const float* W1    = (const float*)d_in[4];
    const float* W2    = (const float*)d_in[5];
    float* out = (float*)d_out;

    const int* row = ei;             // edge_index[0]
    const int* col = ei + N_EDGES;   // edge_index[1]

    k_init<<<2048, 256>>>();
    k_deg<<<(N_EDGES + 255) / 256, 256>>>(col);
    k_dinv<<<(N_NODES + 255) / 256, 256>>>();
    k_w12<<<DIM, DIM>>>(W0, W1);

    long long threads = (long long)N_ITEMS * 32;
    int pblocks = (int)((threads + 255) / 256);

    k_prop<0><<<pblocks, 256>>>(x, row, col, batch);        // y1 = Â x
    k_prop<1><<<pblocks, 256>>>(nullptr, row, col, batch);  // y2 = Â y1

    k_gemm_leaky<<<(N_NODES + 127) / 128, 256>>>();         // y1 = leaky(y2 @ W12)

    k_prop<2><<<pblocks, 256>>>(nullptr, row, col, batch);  // z = P Â y1

    k_out<<<N_GRAPHS, DIM>>>(W2, out);                      // out = z @ W2
}

// round 2
// speedup vs baseline: 1.0134x; 1.0134x over previous
#include <cuda_runtime.h>
#include <math.h>
#include <stdint.h>

#define N_NODES 100000
#define N_EDGES 640000
#define DIM     128
#define N_GRAPHS 512
#define N_ITEMS (N_EDGES + N_NODES)

// ---------------- device scratch (allocation-free) ----------------
__device__ float g_y1[(size_t)N_NODES * DIM];   // Âx, later x3
__device__ float g_y2[(size_t)N_NODES * DIM];   // Â²x
__device__ float g_dinv[N_NODES];
__device__ int   g_deg[N_NODES];
__device__ float g_Bhi[DIM * DIM];              // tf32-hi of W0@W1
__device__ float g_Blo[DIM * DIM];              // tf32-lo of W0@W1
__device__ float g_z[N_GRAPHS * DIM];           // pooled P·Â·x3

// ---------------- small init: deg=1 (self loop), z=0 ----------------
__global__ void k_init_small() {
    int i = blockIdx.x * blockDim.x + threadIdx.x;
    if (i < N_NODES) g_deg[i] = 1;
    if (i < N_GRAPHS * DIM) g_z[i] = 0.f;
}

__global__ void k_deg(const int* __restrict__ col) {
    int e = blockIdx.x * blockDim.x + threadIdx.x;
    if (e < N_EDGES) atomicAdd(&g_deg[col[e]], 1);
}

__global__ void k_dinv() {
    int v = blockIdx.x * blockDim.x + threadIdx.x;
    if (v < N_NODES) g_dinv[v] = rsqrtf((float)g_deg[v]);
}

// ---------------- W12 = W0 @ W1, split into tf32 hi/lo ----------------
__global__ void k_w12split(const float* __restrict__ W0,
                           const float* __restrict__ W1) {
    int i = blockIdx.x;      // 128
    int j = threadIdx.x;     // 128
    float acc = 0.f;
    #pragma unroll 8
    for (int k = 0; k < DIM; k++)
        acc += W0[i * DIM + k] * W1[k * DIM + j];
    uint32_t hi;
    asm("cvt.rna.tf32.f32 %0, %1;" : "=r"(hi) : "f"(acc));
    float lof = acc - __uint_as_float(hi);
    uint32_t lo;
    asm("cvt.rna.tf32.f32 %0, %1;" : "=r"(lo) : "f"(lof));
    g_Bhi[i * DIM + j] = __uint_as_float(hi);
    g_Blo[i * DIM + j] = __uint_as_float(lo);
}

// ---------------- seed: dst[v] = dinv[v]^2 * src[v] (self loop) -------
// MODE 0: src = x(arg) -> g_y1 ; MODE 1: src = g_y1 -> g_y2
template <int MODE>
__global__ void k_seed(const float* __restrict__ xin) {
    int i = blockIdx.x * blockDim.x + threadIdx.x;   // float4 slot
    if (i >= N_NODES * 32) return;
    int v = i >> 5;
    int f4 = (i & 31) * 4;
    float s = g_dinv[v]; s *= s;
    const float* src = (MODE == 0) ? xin : g_y1;
    float* dst = (MODE == 0) ? g_y1 : g_y2;
    float4 xv = *reinterpret_cast<const float4*>(src + (size_t)v * DIM + f4);
    float4 m = make_float4(xv.x * s, xv.y * s, xv.z * s, xv.w * s);
    *reinterpret_cast<float4*>(dst + (size_t)v * DIM + f4) = m;
}

// ---------------- propagation over edges ----------------
// MODE 0: src x      -> g_y1 (edges only)
// MODE 1: src g_y1   -> g_y2 (edges only)
// MODE 2: src g_y1   -> g_z pooled via batch[col] (edges + self loops)
template <int MODE>
__global__ void k_prop(const float* __restrict__ xin,
                       const int* __restrict__ row,
                       const int* __restrict__ col,
                       const int* __restrict__ batch) {
    long long gt = (long long)blockIdx.x * blockDim.x + threadIdx.x;
    int item = (int)(gt >> 5);
    int lane = (int)(gt & 31);
    int n_items = (MODE == 2) ? N_ITEMS : N_EDGES;
    if (item >= n_items) return;

    int r, c;
    float norm;
    if (item < N_EDGES) {
        r = row[item];
        c = col[item];
        norm = g_dinv[r] * g_dinv[c];
    } else {
        r = c = item - N_EDGES;
        float dv = g_dinv[r];
        norm = dv * dv;
    }

    const float* src = (MODE == 0) ? xin : g_y1;
    const float4 v = *reinterpret_cast<const float4*>(src + (size_t)r * DIM + lane * 4);
    float4 m = make_float4(v.x * norm, v.y * norm, v.z * norm, v.w * norm);

    float* dst;
    if (MODE == 2) {
        dst = g_z + (size_t)batch[c] * DIM + lane * 4;
    } else {
        float* base = (MODE == 0) ? g_y1 : g_y2;
        dst = base + (size_t)c * DIM + lane * 4;
    }
    asm volatile("red.global.add.v4.f32 [%0], {%1, %2, %3, %4};"
                 :: "l"(dst), "f"(m.x), "f"(m.y), "f"(m.z), "f"(m.w)
                 : "memory");
}

// ---------------- x3 = leaky_relu(y2 @ W12) -> y1 (tf32 tensor cores) --
// Block: 128x128 C tile, 8 warps (2x4). Warp tile 64x32 = 4x4 m16n8 atoms.
// 3xTF32: D += Ah*Bh + Ah*Bl + Al*Bh  (fp32-grade accuracy).
#define GK 16
#define SA_STRIDE 20    // (20*row + k) % 32 conflict-free for frag loads
#define SB_STRIDE 136   // (136*k + n) % 32 = (8k + n) % 32 conflict-free

__device__ __forceinline__ void mma_tf32(float* c, const uint32_t* a,
                                         const uint32_t* b) {
    asm volatile(
        "mma.sync.aligned.m16n8k8.row.col.f32.tf32.tf32.f32 "
        "{%0,%1,%2,%3}, {%4,%5,%6,%7}, {%8,%9}, {%0,%1,%2,%3};"
        : "+f"(c[0]), "+f"(c[1]), "+f"(c[2]), "+f"(c[3])
        : "r"(a[0]), "r"(a[1]), "r"(a[2]), "r"(a[3]), "r"(b[0]), "r"(b[1]));
}

__global__ void __launch_bounds__(256) k_gemm_tc() {
    __shared__ float sA[128 * SA_STRIDE];
    __shared__ float sBhi[GK * SB_STRIDE];
    __shared__ float sBlo[GK * SB_STRIDE];

    int t = threadIdx.x;
    int warp = t >> 5, lane = t & 31;
    int wm = warp >> 2, wn = warp & 3;        // warp tile: rows wm*64, cols wn*32
    int group = lane >> 2, tg = lane & 3;
    int i0 = blockIdx.x * 128;

    float acc[4][4][4];
    #pragma unroll
    for (int a = 0; a < 4; a++)
        #pragma unroll
        for (int b = 0; b < 4; b++)
            #pragma unroll
            for (int c = 0; c < 4; c++) acc[a][b][c] = 0.f;

    for (int k0 = 0; k0 < DIM; k0 += GK) {
        // ---- load A tile: 128 rows x GK cols (512 float4) ----
        #pragma unroll
        for (int l = 0; l < 2; l++) {
            int q = t + l * 256;            // 0..511
            int rrow = q >> 2;
            int kq = (q & 3) * 4;
            float4 v = make_float4(0.f, 0.f, 0.f, 0.f);
            int gr = i0 + rrow;
            if (gr < N_NODES)
                v = *reinterpret_cast<const float4*>(
                        &g_y2[(size_t)gr * DIM + k0 + kq]);
            *reinterpret_cast<float4*>(&sA[rrow * SA_STRIDE + kq]) = v;
        }
        // ---- load B hi/lo tiles: GK x 128 each (512 float4 apiece over 2 iters) ----
        #pragma unroll
        for (int l = 0; l < 2; l++) {
            int q = t + l * 256;            // 0..511
            int kr = q >> 5;                // 0..15
            int n4 = (q & 31) * 4;
            *reinterpret_cast<float4*>(&sBhi[kr * SB_STRIDE + n4]) =
                *reinterpret_cast<const float4*>(&g_Bhi[(k0 + kr) * DIM + n4]);
            *reinterpret_cast<float4*>(&sBlo[kr * SB_STRIDE + n4]) =
                *reinterpret_cast<const float4*>(&g_Blo[(k0 + kr) * DIM + n4]);
        }
        __syncthreads();

        #pragma unroll
        for (int kk = 0; kk < GK / 8; kk++) {
            int kb = kk * 8;
            // B fragments
            uint32_t bh[4][2], bl[4][2];
            #pragma unroll
            for (int nn = 0; nn < 4; nn++) {
                int n = wn * 32 + nn * 8 + group;
                bh[nn][0] = __float_as_uint(sBhi[(kb + tg) * SB_STRIDE + n]);
                bh[nn][1] = __float_as_uint(sBhi[(kb + tg + 4) * SB_STRIDE + n]);
                bl[nn][0] = __float_as_uint(sBlo[(kb + tg) * SB_STRIDE + n]);
                bl[nn][1] = __float_as_uint(sBlo[(kb + tg + 4) * SB_STRIDE + n]);
            }
            // A fragments (split to hi/lo in registers)
            uint32_t ah[4][4], al[4][4];
            #pragma unroll
            for (int mm = 0; mm < 4; mm++) {
                int r0 = wm * 64 + mm * 16 + group;
                #pragma unroll
                for (int e = 0; e < 4; e++) {
                    int rr = r0 + ((e & 1) ? 8 : 0);
                    int cc = kb + tg + ((e & 2) ? 4 : 0);
                    float a = sA[rr * SA_STRIDE + cc];
                    uint32_t hi;
                    asm("cvt.rna.tf32.f32 %0, %1;" : "=r"(hi) : "f"(a));
                    float lof = a - __uint_as_float(hi);
                    uint32_t lo;
                    asm("cvt.rna.tf32.f32 %0, %1;" : "=r"(lo) : "f"(lof));
                    ah[mm][e] = hi;
                    al[mm][e] = lo;
                }
            }
            #pragma unroll
            for (int mm = 0; mm < 4; mm++)
                #pragma unroll
                for (int nn = 0; nn < 4; nn++) {
                    mma_tf32(acc[mm][nn], ah[mm], bh[nn]);
                    mma_tf32(acc[mm][nn], ah[mm], bl[nn]);
                    mma_tf32(acc[mm][nn], al[mm], bh[nn]);
                }
        }
        __syncthreads();
    }

    // ---- epilogue: leaky relu, store to g_y1 ----
    #pragma unroll
    for (int mm = 0; mm < 4; mm++) {
        #pragma unroll
        for (int nn = 0; nn < 4; nn++) {
            int colb = wn * 32 + nn * 8 + tg * 2;
            #pragma unroll
            for (int half = 0; half < 2; half++) {
                int rr = i0 + wm * 64 + mm * 16 + group + half * 8;
                if (rr < N_NODES) {
                    float v0 = acc[mm][nn][half * 2 + 0];
                    float v1 = acc[mm][nn][half * 2 + 1];
                    v0 = (v0 > 0.f) ? v0 : 0.01f * v0;
                    v1 = (v1 > 0.f) ? v1 : 0.01f * v1;
                    *reinterpret_cast<float2*>(&g_y1[(size_t)rr * DIM + colb]) =
                        make_float2(v0, v1);
                }
            }
        }
    }
}

// ---------------- out = g_z @ W2  (512x128x128) ----------------
__global__ void k_out(const float* __restrict__ W2, float* __restrict__ out) {
    __shared__ float sz[DIM];
    int g = blockIdx.x;
    int j = threadIdx.x;
    sz[j] = g_z[g * DIM + j];
    __syncthreads();
    float acc = 0.f;
    #pragma unroll 8
    for (int k = 0; k < DIM; k++)
        acc += sz[k] * W2[k * DIM + j];
    out[g * DIM + j] = acc;
}

// ---------------- launch ----------------
extern "C" void kernel_launch(void* const* d_in, const int* in_sizes, int n_in,
                              void* d_out, int out_size) {
    const float* x     = (const float*)d_in[0];
    const int*   ei    = (const int*)d_in[1];
    const int*   batch = (const int*)d_in[2];
    const float* W0    = (const float*)d_in[3];
    const float* W1    = (const float*)d_in[4];
    const float* W2    = (const float*)d_in[5];
    float* out = (float*)d_out;

    const int* row = ei;
    const int* col = ei + N_EDGES;

    k_init_small<<<(N_NODES + 255) / 256, 256>>>();
    k_deg<<<(N_EDGES + 255) / 256, 256>>>(col);
    k_dinv<<<(N_NODES + 255) / 256, 256>>>();
    k_w12split<<<DIM, DIM>>>(W0, W1);

    int seed_blocks = (N_NODES * 32 + 255) / 256;
    long long ethreads = (long long)N_EDGES * 32;
    int eblocks = (int)((ethreads + 255) / 256);
    long long athreads = (long long)N_ITEMS * 32;
    int ablocks = (int)((athreads + 255) / 256);

    k_seed<0><<<seed_blocks, 256>>>(x);                      // y1 = dinv^2 x
    k_prop<0><<<eblocks, 256>>>(x, row, col, batch);         // y1 += edges(x)
    k_seed<1><<<seed_blocks, 256>>>(nullptr);                // y2 = dinv^2 y1
    k_prop<1><<<eblocks, 256>>>(nullptr, row, col, batch);   // y2 += edges(y1)

    k_gemm_tc<<<(N_NODES + 127) / 128, 256>>>();             // y1 = leaky(y2@W12)

    k_prop<2><<<ablocks, 256>>>(nullptr, row, col, batch);   // z = P Â y1

    k_out<<<N_GRAPHS, DIM>>>(W2, out);
}

// round 3
// speedup vs baseline: 1.0899x; 1.0755x over previous
#include <cuda_runtime.h>
#include <math.h>
#include <stdint.h>

#define N_NODES 100000
#define N_EDGES 640000
#define DIM     128
#define N_GRAPHS 512

#define SCAN_CHUNK 512
#define NB ((N_NODES + SCAN_CHUNK - 1) / SCAN_CHUNK)   // 196

// ---------------- device scratch (allocation-free) ----------------
__device__ float g_y1[(size_t)N_NODES * DIM];
__device__ float g_y2[(size_t)N_NODES * DIM];
__device__ float g_dinv[N_NODES];
__device__ int   g_deg[N_NODES];
__device__ int   g_ptr[N_NODES + 1];
__device__ int   g_cur[N_NODES];
__device__ int   g_rows[N_EDGES];
__device__ int   g_bsum[NB];
__device__ int   g_boff[NB];
__device__ float g_Bhi[DIM * DIM];
__device__ float g_Blo[DIM * DIM];
__device__ float g_z[N_GRAPHS * DIM];

// ---------------- init: deg=1 (self loop), z=0 ----------------
__global__ void k_init_small() {
    int i = blockIdx.x * blockDim.x + threadIdx.x;
    if (i < N_NODES) g_deg[i] = 1;
    if (i < N_GRAPHS * DIM) g_z[i] = 0.f;
}

__global__ void k_deg(const int* __restrict__ col) {
    int e = blockIdx.x * blockDim.x + threadIdx.x;
    if (e < N_EDGES) atomicAdd(&g_deg[col[e]], 1);
}

// ---------------- scan pass 1: per-chunk edge-count sums + dinv -------
__global__ void __launch_bounds__(256) k_scan1() {
    __shared__ int s[256];
    int b = blockIdx.x, t = threadIdx.x;
    int sum = 0;
    #pragma unroll
    for (int l = 0; l < 2; l++) {
        int v = b * SCAN_CHUNK + t + l * 256;
        if (v < N_NODES) {
            int d = g_deg[v];
            g_dinv[v] = rsqrtf((float)d);
            sum += d - 1;                 // edges only (no self loop)
        }
    }
    s[t] = sum;
    __syncthreads();
    for (int off = 128; off > 0; off >>= 1) {
        if (t < off) s[t] += s[t + off];
        __syncthreads();
    }
    if (t == 0) g_bsum[b] = s[0];
}

// ---------------- scan pass 2: exclusive scan of chunk sums ----------
__global__ void __launch_bounds__(256) k_scan2() {
    __shared__ int s[256];
    int t = threadIdx.x;
    s[t] = (t < NB) ? g_bsum[t] : 0;
    __syncthreads();
    for (int off = 1; off < 256; off <<= 1) {
        int tmp = (t >= off) ? s[t - off] : 0;
        __syncthreads();
        s[t] += tmp;
        __syncthreads();
    }
    if (t < NB) g_boff[t] = s[t] - g_bsum[t];   // exclusive
}

// ---------------- scan pass 3: final ptr / cur ------------------------
__global__ void __launch_bounds__(SCAN_CHUNK) k_scan3() {
    __shared__ int s[SCAN_CHUNK];
    int t = threadIdx.x;
    int v = blockIdx.x * SCAN_CHUNK + t;
    int cnt = (v < N_NODES) ? g_deg[v] - 1 : 0;
    s[t] = cnt;
    __syncthreads();
    for (int off = 1; off < SCAN_CHUNK; off <<= 1) {
        int tmp = (t >= off) ? s[t - off] : 0;
        __syncthreads();
        s[t] += tmp;
        __syncthreads();
    }
    if (v < N_NODES) {
        int incl = s[t];
        int p = g_boff[blockIdx.x] + incl - cnt;
        g_ptr[v] = p;
        g_cur[v] = p;
        if (v == N_NODES - 1) g_ptr[N_NODES] = g_boff[blockIdx.x] + incl;
    }
}

// ---------------- scatter edges into CSR ----------------
__global__ void k_scatter(const int* __restrict__ row,
                          const int* __restrict__ col) {
    int e = blockIdx.x * blockDim.x + threadIdx.x;
    if (e < N_EDGES) {
        int c = col[e];
        int pos = atomicAdd(&g_cur[c], 1);
        g_rows[pos] = row[e];
    }
}

// ---------------- W12 = W0 @ W1, tf32 hi/lo split ----------------
__global__ void __launch_bounds__(128) k_w12split(const float* __restrict__ W0,
                                                  const float* __restrict__ W1) {
    __shared__ float sw0[DIM];
    int i = blockIdx.x, j = threadIdx.x;
    sw0[j] = W0[i * DIM + j];
    __syncthreads();
    float a0 = 0.f, a1 = 0.f, a2 = 0.f, a3 = 0.f;
    #pragma unroll
    for (int k = 0; k < DIM; k += 4) {
        a0 += sw0[k + 0] * W1[(k + 0) * DIM + j];
        a1 += sw0[k + 1] * W1[(k + 1) * DIM + j];
        a2 += sw0[k + 2] * W1[(k + 2) * DIM + j];
        a3 += sw0[k + 3] * W1[(k + 3) * DIM + j];
    }
    float acc = (a0 + a1) + (a2 + a3);
    uint32_t hi;
    asm("cvt.rna.tf32.f32 %0, %1;" : "=r"(hi) : "f"(acc));
    float lof = acc - __uint_as_float(hi);
    uint32_t lo;
    asm("cvt.rna.tf32.f32 %0, %1;" : "=r"(lo) : "f"(lof));
    g_Bhi[i * DIM + j] = __uint_as_float(hi);
    g_Blo[i * DIM + j] = __uint_as_float(lo);
}

// ---------------- CSR propagation: one warp per destination node ------
// MODE 0: src = x (arg)  -> g_y1
// MODE 1: src = g_y1     -> g_y2
// MODE 2: src = g_y1     -> red.add into g_z[batch[v]]
template <int MODE>
__global__ void __launch_bounds__(256) k_cprop(const float* __restrict__ xin,
                                               const int* __restrict__ batch) {
    int gw = (blockIdx.x * blockDim.x + threadIdx.x) >> 5;
    int lane = threadIdx.x & 31;
    if (gw >= N_NODES) return;

    const float* src = (MODE == 0) ? xin : g_y1;
    float dv = g_dinv[gw];

    float4 a = *reinterpret_cast<const float4*>(src + (size_t)gw * DIM + lane * 4);
    float s = dv * dv;
    float4 acc = make_float4(a.x * s, a.y * s, a.z * s, a.w * s);

    int beg = g_ptr[gw], end = g_ptr[gw + 1];
    for (int base = beg; base < end; base += 32) {
        int e = base + lane;
        int r = 0;
        float nrm = 0.f;
        if (e < end) {
            r = g_rows[e];
            nrm = dv * __ldg(&g_dinv[r]);
        }
        int cnt = min(32, end - base);
        for (int i = 0; i < cnt; i++) {
            int rr = __shfl_sync(0xffffffffu, r, i);
            float nn = __shfl_sync(0xffffffffu, nrm, i);
            float4 xv = *reinterpret_cast<const float4*>(
                            src + (size_t)rr * DIM + lane * 4);
            acc.x += nn * xv.x;
            acc.y += nn * xv.y;
            acc.z += nn * xv.z;
            acc.w += nn * xv.w;
        }
    }

    if (MODE == 2) {
        float* dst = g_z + (size_t)batch[gw] * DIM + lane * 4;
        asm volatile("red.global.add.v4.f32 [%0], {%1, %2, %3, %4};"
                     :: "l"(dst), "f"(acc.x), "f"(acc.y), "f"(acc.z), "f"(acc.w)
                     : "memory");
    } else {
        float* base_p = (MODE == 0) ? g_y1 : g_y2;
        *reinterpret_cast<float4*>(base_p + (size_t)gw * DIM + lane * 4) = acc;
    }
}

// ---------------- x3 = leaky_relu(y2 @ W12) -> y1 (tf32, 3xTF32) ------
#define GK 16
#define SA_STRIDE 20
#define SB_STRIDE 136

__device__ __forceinline__ void mma_tf32(float* c, const uint32_t* a,
                                         const uint32_t* b) {
    asm volatile(
        "mma.sync.aligned.m16n8k8.row.col.f32.tf32.tf32.f32 "
        "{%0,%1,%2,%3}, {%4,%5,%6,%7}, {%8,%9}, {%0,%1,%2,%3};"
        : "+f"(c[0]), "+f"(c[1]), "+f"(c[2]), "+f"(c[3])
        : "r"(a[0]), "r"(a[1]), "r"(a[2]), "r"(a[3]), "r"(b[0]), "r"(b[1]));
}

__global__ void __launch_bounds__(256) k_gemm_tc() {
    __shared__ float sA[128 * SA_STRIDE];
    __shared__ float sBhi[GK * SB_STRIDE];
    __shared__ float sBlo[GK * SB_STRIDE];

    int t = threadIdx.x;
    int warp = t >> 5, lane = t & 31;
    int wm = warp >> 2, wn = warp & 3;
    int group = lane >> 2, tg = lane & 3;
    int i0 = blockIdx.x * 128;

    float acc[4][4][4];
    #pragma unroll
    for (int a = 0; a < 4; a++)
        #pragma unroll
        for (int b = 0; b < 4; b++)
            #pragma unroll
            for (int c = 0; c < 4; c++) acc[a][b][c] = 0.f;

    for (int k0 = 0; k0 < DIM; k0 += GK) {
        #pragma unroll
        for (int l = 0; l < 2; l++) {
            int q = t + l * 256;
            int rrow = q >> 2;
            int kq = (q & 3) * 4;
            float4 v = make_float4(0.f, 0.f, 0.f, 0.f);
            int gr = i0 + rrow;
            if (gr < N_NODES)
                v = *reinterpret_cast<const float4*>(
                        &g_y2[(size_t)gr * DIM + k0 + kq]);
            *reinterpret_cast<float4*>(&sA[rrow * SA_STRIDE + kq]) = v;
        }
        #pragma unroll
        for (int l = 0; l < 2; l++) {
            int q = t + l * 256;
            int kr = q >> 5;
            int n4 = (q & 31) * 4;
            *reinterpret_cast<float4*>(&sBhi[kr * SB_STRIDE + n4]) =
                *reinterpret_cast<const float4*>(&g_Bhi[(k0 + kr) * DIM + n4]);
            *reinterpret_cast<float4*>(&sBlo[kr * SB_STRIDE + n4]) =
                *reinterpret_cast<const float4*>(&g_Blo[(k0 + kr) * DIM + n4]);
        }
        __syncthreads();

        #pragma unroll
        for (int kk = 0; kk < GK / 8; kk++) {
            int kb = kk * 8;
            uint32_t bh[4][2], bl[4][2];
            #pragma unroll
            for (int nn = 0; nn < 4; nn++) {
                int n = wn * 32 + nn * 8 + group;
                bh[nn][0] = __float_as_uint(sBhi[(kb + tg) * SB_STRIDE + n]);
                bh[nn][1] = __float_as_uint(sBhi[(kb + tg + 4) * SB_STRIDE + n]);
                bl[nn][0] = __float_as_uint(sBlo[(kb + tg) * SB_STRIDE + n]);
                bl[nn][1] = __float_as_uint(sBlo[(kb + tg + 4) * SB_STRIDE + n]);
            }
            uint32_t ah[4][4], al[4][4];
            #pragma unroll
            for (int mm = 0; mm < 4; mm++) {
                int r0 = wm * 64 + mm * 16 + group;
                #pragma unroll
                for (int e = 0; e < 4; e++) {
                    int rr = r0 + ((e & 1) ? 8 : 0);
                    int cc = kb + tg + ((e & 2) ? 4 : 0);
                    float a = sA[rr * SA_STRIDE + cc];
                    uint32_t hi;
                    asm("cvt.rna.tf32.f32 %0, %1;" : "=r"(hi) : "f"(a));
                    float lof = a - __uint_as_float(hi);
                    uint32_t lo;
                    asm("cvt.rna.tf32.f32 %0, %1;" : "=r"(lo) : "f"(lof));
                    ah[mm][e] = hi;
                    al[mm][e] = lo;
                }
            }
            #pragma unroll
            for (int mm = 0; mm < 4; mm++)
                #pragma unroll
                for (int nn = 0; nn < 4; nn++) {
                    mma_tf32(acc[mm][nn], ah[mm], bh[nn]);
                    mma_tf32(acc[mm][nn], ah[mm], bl[nn]);
                    mma_tf32(acc[mm][nn], al[mm], bh[nn]);
                }
        }
        __syncthreads();
    }

    #pragma unroll
    for (int mm = 0; mm < 4; mm++) {
        #pragma unroll
        for (int nn = 0; nn < 4; nn++) {
            int colb = wn * 32 + nn * 8 + tg * 2;
            #pragma unroll
            for (int half = 0; half < 2; half++) {
                int rr = i0 + wm * 64 + mm * 16 + group + half * 8;
                if (rr < N_NODES) {
                    float v0 = acc[mm][nn][half * 2 + 0];
                    float v1 = acc[mm][nn][half * 2 + 1];
                    v0 = (v0 > 0.f) ? v0 : 0.01f * v0;
                    v1 = (v1 > 0.f) ? v1 : 0.01f * v1;
                    *reinterpret_cast<float2*>(&g_y1[(size_t)rr * DIM + colb]) =
                        make_float2(v0, v1);
                }
            }
        }
    }
}

// ---------------- out = g_z @ W2 ----------------
__global__ void k_out(const float* __restrict__ W2, float* __restrict__ out) {
    __shared__ float sz[DIM];
    int g = blockIdx.x;
    int j = threadIdx.x;
    sz[j] = g_z[g * DIM + j];
    __syncthreads();
    float acc = 0.f;
    #pragma unroll 8
    for (int k = 0; k < DIM; k++)
        acc += sz[k] * W2[k * DIM + j];
    out[g * DIM + j] = acc;
}

// ---------------- launch ----------------
extern "C" void kernel_launch(void* const* d_in, const int* in_sizes, int n_in,
                              void* d_out, int out_size) {
    const float* x     = (const float*)d_in[0];
    const int*   ei    = (const int*)d_in[1];
    const int*   batch = (const int*)d_in[2];
    const float* W0    = (const float*)d_in[3];
    const float* W1    = (const float*)d_in[4];
    const float* W2    = (const float*)d_in[5];
    float* out = (float*)d_out;

    const int* row = ei;
    const int* col = ei + N_EDGES;

    k_init_small<<<(N_NODES + 255) / 256, 256>>>();
    k_deg<<<(N_EDGES + 255) / 256, 256>>>(col);
    k_scan1<<<NB, 256>>>();
    k_scan2<<<1, 256>>>();
    k_scan3<<<NB, SCAN_CHUNK>>>();
    k_scatter<<<(N_EDGES + 255) / 256, 256>>>(row, col);
    k_w12split<<<DIM, DIM>>>(W0, W1);

    int pblocks = (N_NODES * 32 + 255) / 256;   // warp per node

    k_cprop<0><<<pblocks, 256>>>(x, batch);        // y1 = Â x
    k_cprop<1><<<pblocks, 256>>>(nullptr, batch);  // y2 = Â y1
    k_gemm_tc<<<(N_NODES + 127) / 128, 256>>>();   // y1 = leaky(y2 @ W12)
    k_cprop<2><<<pblocks, 256>>>(nullptr, batch);  // z = P Â y1
    k_out<<<N_GRAPHS, DIM>>>(W2, out);
}

// round 4
// speedup vs baseline: 1.4639x; 1.3431x over previous
#include <cuda_runtime.h>
#include <math.h>
#include <stdint.h>

#define N_NODES 100000
#define N_EDGES 640000
#define DIM     128
#define N_GRAPHS 512

#define SCAN_CHUNK 512
#define NB ((N_NODES + SCAN_CHUNK - 1) / SCAN_CHUNK)   // 196

// ---------------- device scratch (allocation-free) ----------------
__device__ float g_y1[(size_t)N_NODES * DIM];
__device__ float g_y2[(size_t)N_NODES * DIM];
__device__ float g_dinv[N_NODES];
__device__ int   g_deg[N_NODES];          // edge-only in-degree
__device__ int   g_ptr[N_NODES + 1];
__device__ int   g_cur[N_NODES];
__device__ int   g_rows[N_EDGES];
__device__ float g_enorm[N_EDGES];        // dinv[row]*dinv[col], CSR order
__device__ int   g_bsum[NB];
__device__ float g_Bhi[DIM * DIM];
__device__ float g_Blo[DIM * DIM];
__device__ float g_z[N_GRAPHS * DIM];

// ---------------- init: deg=0, z=0 ----------------
__global__ void k_init_small() {
    int i = blockIdx.x * blockDim.x + threadIdx.x;
    if (i < N_NODES) g_deg[i] = 0;
    if (i < N_GRAPHS * DIM) g_z[i] = 0.f;
}

__global__ void k_deg(const int* __restrict__ col) {
    int e = blockIdx.x * blockDim.x + threadIdx.x;
    if (e < N_EDGES) atomicAdd(&g_deg[col[e]], 1);
}

// ---------------- scan pass 1: per-chunk sums + dinv ----------------
__global__ void __launch_bounds__(256) k_scan1() {
    __shared__ int s[256];
    int b = blockIdx.x, t = threadIdx.x;
    int sum = 0;
    #pragma unroll
    for (int l = 0; l < 2; l++) {
        int v = b * SCAN_CHUNK + t + l * 256;
        if (v < N_NODES) {
            int d = g_deg[v];
            g_dinv[v] = rsqrtf((float)(d + 1));   // +1 self loop
            sum += d;
        }
    }
    s[t] = sum;
    __syncthreads();
    for (int off = 128; off > 0; off >>= 1) {
        if (t < off) s[t] += s[t + off];
        __syncthreads();
    }
    if (t == 0) g_bsum[b] = s[0];
}

// ---------------- scan pass 2 (fused): ptr / cur ----------------
__global__ void __launch_bounds__(SCAN_CHUNK) k_scan3() {
    __shared__ int s[SCAN_CHUNK];
    __shared__ int sb[256];
    int t = threadIdx.x;

    // each block scans the 196 chunk sums itself (fused old k_scan2)
    if (t < 256) sb[t] = (t < NB) ? g_bsum[t] : 0;
    __syncthreads();
    for (int off = 1; off < 256; off <<= 1) {
        int tmp = (t < 256 && t >= off) ? sb[t - off] : 0;
        __syncthreads();
        if (t < 256) sb[t] += tmp;
        __syncthreads();
    }
    int boff = (blockIdx.x == 0) ? 0 : sb[blockIdx.x - 1];

    int v = blockIdx.x * SCAN_CHUNK + t;
    int cnt = (v < N_NODES) ? g_deg[v] : 0;
    s[t] = cnt;
    __syncthreads();
    for (int off = 1; off < SCAN_CHUNK; off <<= 1) {
        int tmp = (t >= off) ? s[t - off] : 0;
        __syncthreads();
        s[t] += tmp;
        __syncthreads();
    }
    if (v < N_NODES) {
        int incl = s[t];
        int p = boff + incl - cnt;
        g_ptr[v] = p;
        g_cur[v] = p;
        if (v == N_NODES - 1) g_ptr[N_NODES] = boff + incl;
    }
}

// ---------------- scatter edges into CSR (+ per-edge norm) ------------
__global__ void k_scatter(const int* __restrict__ row,
                          const int* __restrict__ col) {
    int e = blockIdx.x * blockDim.x + threadIdx.x;
    if (e < N_EDGES) {
        int r = row[e];
        int c = col[e];
        int pos = atomicAdd(&g_cur[c], 1);
        g_rows[pos] = r;
        g_enorm[pos] = g_dinv[r] * g_dinv[c];
    }
}

// ---------------- W12 = W0 @ W1, tf32 hi/lo split ----------------
__global__ void __launch_bounds__(128) k_w12split(const float* __restrict__ W0,
                                                  const float* __restrict__ W1) {
    __shared__ float sw0[DIM];
    int i = blockIdx.x, j = threadIdx.x;
    sw0[j] = W0[i * DIM + j];
    __syncthreads();
    float a0 = 0.f, a1 = 0.f, a2 = 0.f, a3 = 0.f;
    #pragma unroll
    for (int k = 0; k < DIM; k += 4) {
        a0 += sw0[k + 0] * W1[(k + 0) * DIM + j];
        a1 += sw0[k + 1] * W1[(k + 1) * DIM + j];
        a2 += sw0[k + 2] * W1[(k + 2) * DIM + j];
        a3 += sw0[k + 3] * W1[(k + 3) * DIM + j];
    }
    float acc = (a0 + a1) + (a2 + a3);
    uint32_t hi;
    asm("cvt.rna.tf32.f32 %0, %1;" : "=r"(hi) : "f"(acc));
    float lof = acc - __uint_as_float(hi);
    uint32_t lo;
    asm("cvt.rna.tf32.f32 %0, %1;" : "=r"(lo) : "f"(lof));
    g_Bhi[i * DIM + j] = __uint_as_float(hi);
    g_Blo[i * DIM + j] = __uint_as_float(lo);
}

// ---------------- CSR propagation: warp per node, MLP-4 gather --------
// MODE 0: src = x (arg)  -> g_y1
// MODE 1: src = g_y1     -> g_y2
// MODE 2: src = g_y1     -> red.add into g_z[batch[v]]
template <int MODE>
__global__ void __launch_bounds__(256) k_cprop(const float* __restrict__ xin,
                                               const int* __restrict__ batch) {
    int gw = (blockIdx.x * blockDim.x + threadIdx.x) >> 5;
    int lane = threadIdx.x & 31;
    if (gw >= N_NODES) return;

    const float* src = (MODE == 0) ? xin : g_y1;
    float dv = g_dinv[gw];

    float4 a = *reinterpret_cast<const float4*>(src + (size_t)gw * DIM + lane * 4);
    float s = dv * dv;
    float4 acc = make_float4(a.x * s, a.y * s, a.z * s, a.w * s);

    int beg = g_ptr[gw], end = g_ptr[gw + 1];
    for (int base = beg; base < end; base += 32) {
        int idx = base + lane;
        int r = 0;
        float nrm = 0.f;
        if (idx < end) {
            r = g_rows[idx];
            nrm = g_enorm[idx];
        }
        int cnt = min(32, end - base);
        int i = 0;
        for (; i + 4 <= cnt; i += 4) {
            int r0 = __shfl_sync(0xffffffffu, r, i + 0);
            int r1 = __shfl_sync(0xffffffffu, r, i + 1);
            int r2 = __shfl_sync(0xffffffffu, r, i + 2);
            int r3 = __shfl_sync(0xffffffffu, r, i + 3);
            float n0 = __shfl_sync(0xffffffffu, nrm, i + 0);
            float n1 = __shfl_sync(0xffffffffu, nrm, i + 1);
            float n2 = __shfl_sync(0xffffffffu, nrm, i + 2);
            float n3 = __shfl_sync(0xffffffffu, nrm, i + 3);
            const float4 x0 = *reinterpret_cast<const float4*>(
                                  src + (size_t)r0 * DIM + lane * 4);
            const float4 x1 = *reinterpret_cast<const float4*>(
                                  src + (size_t)r1 * DIM + lane * 4);
            const float4 x2 = *reinterpret_cast<const float4*>(
                                  src + (size_t)r2 * DIM + lane * 4);
            const float4 x3 = *reinterpret_cast<const float4*>(
                                  src + (size_t)r3 * DIM + lane * 4);
            acc.x += n0 * x0.x; acc.y += n0 * x0.y;
            acc.z += n0 * x0.z; acc.w += n0 * x0.w;
            acc.x += n1 * x1.x; acc.y += n1 * x1.y;
            acc.z += n1 * x1.z; acc.w += n1 * x1.w;
            acc.x += n2 * x2.x; acc.y += n2 * x2.y;
            acc.z += n2 * x2.z; acc.w += n2 * x2.w;
            acc.x += n3 * x3.x; acc.y += n3 * x3.y;
            acc.z += n3 * x3.z; acc.w += n3 * x3.w;
        }
        for (; i < cnt; i++) {
            int rr = __shfl_sync(0xffffffffu, r, i);
            float nn = __shfl_sync(0xffffffffu, nrm, i);
            const float4 xv = *reinterpret_cast<const float4*>(
                                  src + (size_t)rr * DIM + lane * 4);
            acc.x += nn * xv.x; acc.y += nn * xv.y;
            acc.z += nn * xv.z; acc.w += nn * xv.w;
        }
    }

    if (MODE == 2) {
        float* dst = g_z + (size_t)batch[gw] * DIM + lane * 4;
        asm volatile("red.global.add.v4.f32 [%0], {%1, %2, %3, %4};"
                     :: "l"(dst), "f"(acc.x), "f"(acc.y), "f"(acc.z), "f"(acc.w)
                     : "memory");
    } else {
        float* base_p = (MODE == 0) ? g_y1 : g_y2;
        *reinterpret_cast<float4*>(base_p + (size_t)gw * DIM + lane * 4) = acc;
    }
}

// ---------------- x3 = leaky_relu(y2 @ W12) -> y1 (tf32, 3xTF32) ------
#define GK 16
#define SA_STRIDE 20
#define SB_STRIDE 136

__device__ __forceinline__ void mma_tf32(float* c, const uint32_t* a,
                                         const uint32_t* b) {
    asm volatile(
        "mma.sync.aligned.m16n8k8.row.col.f32.tf32.tf32.f32 "
        "{%0,%1,%2,%3}, {%4,%5,%6,%7}, {%8,%9}, {%0,%1,%2,%3};"
        : "+f"(c[0]), "+f"(c[1]), "+f"(c[2]), "+f"(c[3])
        : "r"(a[0]), "r"(a[1]), "r"(a[2]), "r"(a[3]), "r"(b[0]), "r"(b[1]));
}

__global__ void __launch_bounds__(256) k_gemm_tc() {
    __shared__ float sA[128 * SA_STRIDE];
    __shared__ float sBhi[GK * SB_STRIDE];
    __shared__ float sBlo[GK * SB_STRIDE];

    int t = threadIdx.x;
    int warp = t >> 5, lane = t & 31;
    int wm = warp >> 2, wn = warp & 3;
    int group = lane >> 2, tg = lane & 3;
    int i0 = blockIdx.x * 128;

    float acc[4][4][4];
    #pragma unroll
    for (int a = 0; a < 4; a++)
        #pragma unroll
        for (int b = 0; b < 4; b++)
            #pragma unroll
            for (int c = 0; c < 4; c++) acc[a][b][c] = 0.f;

    for (int k0 = 0; k0 < DIM; k0 += GK) {
        #pragma unroll
        for (int l = 0; l < 2; l++) {
            int q = t + l * 256;
            int rrow = q >> 2;
            int kq = (q & 3) * 4;
            float4 v = make_float4(0.f, 0.f, 0.f, 0.f);
            int gr = i0 + rrow;
            if (gr < N_NODES)
                v = *reinterpret_cast<const float4*>(
                        &g_y2[(size_t)gr * DIM + k0 + kq]);
            *reinterpret_cast<float4*>(&sA[rrow * SA_STRIDE + kq]) = v;
        }
        #pragma unroll
        for (int l = 0; l < 2; l++) {
            int q = t + l * 256;
            int kr = q >> 5;
            int n4 = (q & 31) * 4;
            *reinterpret_cast<float4*>(&sBhi[kr * SB_STRIDE + n4]) =
                *reinterpret_cast<const float4*>(&g_Bhi[(k0 + kr) * DIM + n4]);
            *reinterpret_cast<float4*>(&sBlo[kr * SB_STRIDE + n4]) =
                *reinterpret_cast<const float4*>(&g_Blo[(k0 + kr) * DIM + n4]);
        }
        __syncthreads();

        #pragma unroll
        for (int kk = 0; kk < GK / 8; kk++) {
            int kb = kk * 8;
            uint32_t bh[4][2], bl[4][2];
            #pragma unroll
            for (int nn = 0; nn < 4; nn++) {
                int n = wn * 32 + nn * 8 + group;
                bh[nn][0] = __float_as_uint(sBhi[(kb + tg) * SB_STRIDE + n]);
                bh[nn][1] = __float_as_uint(sBhi[(kb + tg + 4) * SB_STRIDE + n]);
                bl[nn][0] = __float_as_uint(sBlo[(kb + tg) * SB_STRIDE + n]);
                bl[nn][1] = __float_as_uint(sBlo[(kb + tg + 4) * SB_STRIDE + n]);
            }
            uint32_t ah[4][4], al[4][4];
            #pragma unroll
            for (int mm = 0; mm < 4; mm++) {
                int r0 = wm * 64 + mm * 16 + group;
                #pragma unroll
                for (int e = 0; e < 4; e++) {
                    int rr = r0 + ((e & 1) ? 8 : 0);
                    int cc = kb + tg + ((e & 2) ? 4 : 0);
                    float a = sA[rr * SA_STRIDE + cc];
                    uint32_t hi;
                    asm("cvt.rna.tf32.f32 %0, %1;" : "=r"(hi) : "f"(a));
                    float lof = a - __uint_as_float(hi);
                    uint32_t lo;
                    asm("cvt.rna.tf32.f32 %0, %1;" : "=r"(lo) : "f"(lof));
                    ah[mm][e] = hi;
                    al[mm][e] = lo;
                }
            }
            #pragma unroll
            for (int mm = 0; mm < 4; mm++)
                #pragma unroll
                for (int nn = 0; nn < 4; nn++) {
                    mma_tf32(acc[mm][nn], ah[mm], bh[nn]);
                    mma_tf32(acc[mm][nn], ah[mm], bl[nn]);
                    mma_tf32(acc[mm][nn], al[mm], bh[nn]);
                }
        }
        __syncthreads();
    }

    #pragma unroll
    for (int mm = 0; mm < 4; mm++) {
        #pragma unroll
        for (int nn = 0; nn < 4; nn++) {
            int colb = wn * 32 + nn * 8 + tg * 2;
            #pragma unroll
            for (int half = 0; half < 2; half++) {
                int rr = i0 + wm * 64 + mm * 16 + group + half * 8;
                if (rr < N_NODES) {
                    float v0 = acc[mm][nn][half * 2 + 0];
                    float v1 = acc[mm][nn][half * 2 + 1];
                    v0 = (v0 > 0.f) ? v0 : 0.01f * v0;
                    v1 = (v1 > 0.f) ? v1 : 0.01f * v1;
                    *reinterpret_cast<float2*>(&g_y1[(size_t)rr * DIM + colb]) =
                        make_float2(v0, v1);
                }
            }
        }
    }
}

// ---------------- out = g_z @ W2 ----------------
__global__ void k_out(const float* __restrict__ W2, float* __restrict__ out) {
    __shared__ float sz[DIM];
    int g = blockIdx.x;
    int j = threadIdx.x;
    sz[j] = g_z[g * DIM + j];
    __syncthreads();
    float acc = 0.f;
    #pragma unroll 8
    for (int k = 0; k < DIM; k++)
        acc += sz[k] * W2[k * DIM + j];
    out[g * DIM + j] = acc;
}

// ---------------- launch ----------------
extern "C" void kernel_launch(void* const* d_in, const int* in_sizes, int n_in,
                              void* d_out, int out_size) {
    const float* x     = (const float*)d_in[0];
    const int*   ei    = (const int*)d_in[1];
    const int*   batch = (const int*)d_in[2];
    const float* W0    = (const float*)d_in[3];
    const float* W1    = (const float*)d_in[4];
    const float* W2    = (const float*)d_in[5];
    float* out = (float*)d_out;

    const int* row = ei;
    const int* col = ei + N_EDGES;

    k_init_small<<<(N_NODES + 255) / 256, 256>>>();
    k_deg<<<(N_EDGES + 255) / 256, 256>>>(col);
    k_scan1<<<NB, 256>>>();
    k_scan3<<<NB, SCAN_CHUNK>>>();
    k_scatter<<<(N_EDGES + 255) / 256, 256>>>(row, col);
    k_w12split<<<DIM, DIM>>>(W0, W1);

    int pblocks = (N_NODES * 32 + 255) / 256;

    k_cprop<0><<<pblocks, 256>>>(x, batch);
    k_cprop<1><<<pblocks, 256>>>(nullptr, batch);
    k_gemm_tc<<<(N_NODES + 127) / 128, 256>>>();
    k_cprop<2><<<pblocks, 256>>>(nullptr, batch);
    k_out<<<N_GRAPHS, DIM>>>(W2, out);
}